// round 8
// baseline (speedup 1.0000x reference)
#include <cuda_runtime.h>
#include <cstdint>
#include <math.h>

#define T_STEPS 256
#define BATCH   64
#define HID     256
#define G3      768           // 3*HID
#define VOCAB   5000

typedef unsigned long long u64;

// Scratch (static __device__ arrays: allowed; no runtime allocation)
__device__ float g_MX[(size_t)T_STEPS * BATCH * G3];   // [t][b][3H], includes b_in
__device__ float g_Y [(size_t)T_STEPS * BATCH * HID];  // [t][b][H]

// ---------------------------------------------------------------------------
// Kernel 1: MX[t][b][n] = kernel[tokens[b][t]][n] + b_in[n]   (gather)
// ---------------------------------------------------------------------------
__global__ void mx_kernel(const int* __restrict__ tokens,
                          const float* __restrict__ Wk,
                          const float* __restrict__ bias) {
    int idx = blockIdx.x * 256 + threadIdx.x;       // exactly T*B*G3 threads
    int n  = idx % G3;
    int tb = idx / G3;
    int b  = tb % BATCH;
    int t  = tb / BATCH;
    int tok = tokens[b * T_STEPS + t];
    g_MX[idx] = Wk[(size_t)tok * G3 + n] + bias[n];
}

// ---------------------------------------------------------------------------
// Kernel 2: GRU scan, register-resident weights + fp32x2 packed FMA.
// 16 clusters x 8 CTAs x 256 threads. Cluster owns 4 sequences.
// CTA rank r owns hidden cols c in [r*32, r*32+32), all 3 gates.
// Thread (jj 0..31, o 0..7), tid = jj*8+o: holds w[3 gates][k in o*32..o*32+32)
// in registers as 48 packed f32x2 (k-pairs). Each step: 192 fma.f32x2,
// butterfly shfl_xor over o -> every lane has full dot products -> lane o
// stores h_new to cluster rank o's SMEM h buffer (DSMEM), one cluster
// barrier per step, parity double-buffered h.
// ---------------------------------------------------------------------------
__device__ __forceinline__ uint32_t smem_u32(const void* p) {
    uint32_t a;
    asm("{ .reg .u64 t; cvta.to.shared.u64 t, %1; cvt.u32.u64 %0, t; }"
        : "=r"(a) : "l"(p));
    return a;
}
__device__ __forceinline__ void st_cluster_f32(uint32_t laddr, int rank, float v) {
    uint32_t ra;
    asm volatile("mapa.shared::cluster.u32 %0, %1, %2;" : "=r"(ra) : "r"(laddr), "r"(rank));
    asm volatile("st.shared::cluster.f32 [%0], %1;" :: "r"(ra), "f"(v) : "memory");
}
__device__ __forceinline__ u64 fma2(u64 a, u64 b, u64 c) {
    u64 d;
    asm("fma.rn.f32x2 %0, %1, %2, %3;" : "=l"(d) : "l"(a), "l"(b), "l"(c));
    return d;
}
__device__ __forceinline__ u64 packf2(float lo, float hi) {
    return (u64)__float_as_uint(lo) | ((u64)__float_as_uint(hi) << 32);
}
__device__ __forceinline__ float sumf2(u64 p) {
    return __uint_as_float((unsigned)p) + __uint_as_float((unsigned)(p >> 32));
}
__device__ __forceinline__ float sigmoidf_(float x) { return 1.0f / (1.0f + __expf(-x)); }

#define HPAD 288   // 256 cols + 4-float pad per 32 -> conflict-free across o

__global__ void __cluster_dims__(8, 1, 1) __launch_bounds__(256, 1) scan_kernel(
    const float* __restrict__ h0,
    const float* __restrict__ rkernel,
    const float* __restrict__ bias,
    float* __restrict__ out, int write_hlast)
{
    __shared__ float hb[2][4][HPAD];     // [parity][seq][padded col]
    const int tid = threadIdx.x;         // = jj*8 + o
    const int jj = tid >> 3;             // 0..31: local hidden col
    const int o  = tid & 7;              // 0..7 : k-octant AND target cluster rank
    uint32_t crank;
    asm("mov.u32 %0, %%cluster_ctarank;" : "=r"(crank));
    const int cid  = blockIdx.x >> 3;    // 0..15
    const int seq0 = cid * 4;
    const int c    = (int)crank * 32 + jj;      // global hidden col 0..255
    const int kbase = o * 32;

    // ---- load weight slice into registers (k-pairs packed for f32x2) ----
    u64 w2[3][16];
    #pragma unroll
    for (int g = 0; g < 3; ++g) {
        #pragma unroll
        for (int ii = 0; ii < 16; ++ii) {
            float a = rkernel[(size_t)(kbase + 2 * ii)     * G3 + g * HID + c];
            float b = rkernel[(size_t)(kbase + 2 * ii + 1) * G3 + g * HID + c];
            w2[g][ii] = packf2(a, b);
        }
    }
    const float brz = bias[G3 + c];
    const float brr = bias[G3 + HID + c];
    const float brh = bias[G3 + 2 * HID + c];

    // ---- init h buffer parity 0 (padded layout) ----
    for (int e = tid; e < 4 * HID; e += 256) {
        int s = e >> 8, k = e & 255;
        hb[0][s][k + ((k >> 5) << 2)] = h0[(size_t)(seq0 + s) * HID + k];
    }
    const uint32_t hb_base = smem_u32(&hb[0][0][0]);
    const int padc = (int)crank * 36 + jj;      // padded index of col c
    __syncthreads();
    asm volatile("barrier.cluster.arrive.aligned;" ::: "memory");
    asm volatile("barrier.cluster.wait.aligned;"   ::: "memory");

    for (int t = 0; t < T_STEPS; ++t) {
        const int cur = t & 1, nxt = cur ^ 1;

        // Prefetch MX for this step (consumed after reduction -> latency hidden)
        const float* mxp = g_MX + ((size_t)t * BATCH + seq0) * G3 + c;
        float mxz[4], mxr[4], mxh[4];
        #pragma unroll
        for (int s = 0; s < 4; ++s) {
            mxz[s] = mxp[(size_t)s * G3];
            mxr[s] = mxp[(size_t)s * G3 + HID];
            mxh[s] = mxp[(size_t)s * G3 + 2 * HID];
        }

        // ---- packed matvec: acc[g][s] over my k-octant ----
        u64 acc[3][4];
        #pragma unroll
        for (int g = 0; g < 3; ++g)
            #pragma unroll
            for (int s = 0; s < 4; ++s) acc[g][s] = 0ull;

        #pragma unroll
        for (int s = 0; s < 4; ++s) {
            const float* hrow = &hb[cur][s][o * 36];   // 32 floats, 16B aligned
            #pragma unroll
            for (int q = 0; q < 8; ++q) {              // 4 k per iter = 2 pairs
                ulonglong2 hp = *reinterpret_cast<const ulonglong2*>(hrow + q * 4);
                #pragma unroll
                for (int g = 0; g < 3; ++g) {
                    acc[g][s] = fma2(w2[g][2 * q],     hp.x, acc[g][s]);
                    acc[g][s] = fma2(w2[g][2 * q + 1], hp.y, acc[g][s]);
                }
            }
        }

        // ---- collapse pairs, butterfly-reduce over o (lanes: (jj&3)*8 + o) ----
        float red[12];
        #pragma unroll
        for (int g = 0; g < 3; ++g)
            #pragma unroll
            for (int s = 0; s < 4; ++s) red[g * 4 + s] = sumf2(acc[g][s]);
        #pragma unroll
        for (int m = 1; m <= 4; m <<= 1)
            #pragma unroll
            for (int v = 0; v < 12; ++v)
                red[v] += __shfl_xor_sync(0xFFFFFFFFu, red[v], m);

        // ---- gates (all lanes redundantly; each lane stores to rank o) ----
        float hn[4];
        #pragma unroll
        for (int s = 0; s < 4; ++s) {
            float az = red[s], ar = red[4 + s], ah = red[8 + s];
            float z = sigmoidf_(mxz[s] + az + brz);
            float r = sigmoidf_(mxr[s] + ar + brr);
            float cand = tanhf(mxh[s] + r * (ah + brh));
            float hp0 = hb[cur][s][padc];
            hn[s] = z * hp0 + (1.0f - z) * cand;
        }

        // Remote store h_new for my col into rank o's next-parity buffer
        #pragma unroll
        for (int s = 0; s < 4; ++s) {
            uint32_t la = hb_base + (uint32_t)(((nxt * 4 + s) * HPAD + padc) * 4);
            st_cluster_f32(la, o, hn[s]);
        }

        asm volatile("barrier.cluster.arrive.aligned;" ::: "memory");

        // Overlap with barrier: global Y store (one o-lane per col)
        if (o == 0) {
            #pragma unroll
            for (int s = 0; s < 4; ++s)
                g_Y[((size_t)t * BATCH + seq0 + s) * HID + c] = hn[s];
            if (write_hlast && t == T_STEPS - 1) {
                size_t hl = (size_t)VOCAB * (T_STEPS * BATCH);
                #pragma unroll
                for (int s = 0; s < 4; ++s)
                    out[hl + (size_t)(seq0 + s) * HID + c] = hn[s];
            }
        }

        asm volatile("barrier.cluster.wait.aligned;" ::: "memory");
    }
}

// ---------------------------------------------------------------------------
// Kernel 3: out = Y[16384,256] @ Wd[256,5000] + bd, tf32 mma.sync (m16n8k8)
// 128x128 tiles, BK=32, 8 warps (2x4), warp tile 64x32.  (unchanged: known good)
// ---------------------------------------------------------------------------
__device__ __forceinline__ uint32_t f2tf(float f) {
    uint32_t u;
    asm("cvt.rna.tf32.f32 %0, %1;" : "=r"(u) : "f"(f));
    return u;
}
__device__ __forceinline__ void mma_tf32(float d[4], const uint32_t a[4], const uint32_t b[2]) {
    asm volatile(
        "mma.sync.aligned.m16n8k8.row.col.f32.tf32.tf32.f32 "
        "{%0,%1,%2,%3}, {%4,%5,%6,%7}, {%8,%9}, {%0,%1,%2,%3};\n"
        : "+f"(d[0]), "+f"(d[1]), "+f"(d[2]), "+f"(d[3])
        : "r"(a[0]), "r"(a[1]), "r"(a[2]), "r"(a[3]), "r"(b[0]), "r"(b[1]));
}

__global__ void __launch_bounds__(256) proj_kernel(
    const float* __restrict__ Wd, const float* __restrict__ bd,
    float* __restrict__ out)
{
    __shared__ uint32_t As[128 * 33];   // [row][k], stride 33
    __shared__ uint32_t Bs[32 * 132];   // [k][col], stride 132
    const int tid  = threadIdx.x;
    const int lane = tid & 31, wid = tid >> 5;
    const int wr = wid >> 2, wc = wid & 3;       // warp grid 2x4
    const int n0 = blockIdx.x * 128;
    const int i0 = blockIdx.y * 128;

    float acc[4][4][4];
    #pragma unroll
    for (int mi = 0; mi < 4; mi++)
        #pragma unroll
        for (int ni = 0; ni < 4; ni++)
            #pragma unroll
            for (int q = 0; q < 4; q++) acc[mi][ni][q] = 0.0f;

    for (int k0 = 0; k0 < HID; k0 += 32) {
        // A: Y tile 128x32
        for (int e = tid; e < 1024; e += 256) {
            int row = e >> 3;
            int c4  = (e & 7) << 2;
            float4 v = *reinterpret_cast<const float4*>(
                &g_Y[(size_t)(i0 + row) * HID + k0 + c4]);
            As[row * 33 + c4 + 0] = f2tf(v.x);
            As[row * 33 + c4 + 1] = f2tf(v.y);
            As[row * 33 + c4 + 2] = f2tf(v.z);
            As[row * 33 + c4 + 3] = f2tf(v.w);
        }
        // B: Wd tile 32x128 (zero-fill past VOCAB)
        for (int e = tid; e < 1024; e += 256) {
            int row = e >> 5;
            int c4  = (e & 31) << 2;
            int col = n0 + c4;
            float4 v = make_float4(0.f, 0.f, 0.f, 0.f);
            if (col < VOCAB)
                v = *reinterpret_cast<const float4*>(
                    &Wd[(size_t)(k0 + row) * VOCAB + col]);
            Bs[row * 132 + c4 + 0] = f2tf(v.x);
            Bs[row * 132 + c4 + 1] = f2tf(v.y);
            Bs[row * 132 + c4 + 2] = f2tf(v.z);
            Bs[row * 132 + c4 + 3] = f2tf(v.w);
        }
        __syncthreads();
        #pragma unroll
        for (int kk = 0; kk < 32; kk += 8) {
            uint32_t a[4][4], b[4][2];
            #pragma unroll
            for (int mi = 0; mi < 4; mi++) {
                int ar = wr * 64 + mi * 16 + (lane >> 2);
                int ac = kk + (lane & 3);
                a[mi][0] = As[ar * 33 + ac];
                a[mi][1] = As[(ar + 8) * 33 + ac];
                a[mi][2] = As[ar * 33 + ac + 4];
                a[mi][3] = As[(ar + 8) * 33 + ac + 4];
            }
            #pragma unroll
            for (int ni = 0; ni < 4; ni++) {
                int bc = wc * 32 + ni * 8 + (lane >> 2);
                int br = kk + (lane & 3);
                b[ni][0] = Bs[br * 132 + bc];
                b[ni][1] = Bs[(br + 4) * 132 + bc];
            }
            #pragma unroll
            for (int mi = 0; mi < 4; mi++)
                #pragma unroll
                for (int ni = 0; ni < 4; ni++)
                    mma_tf32(acc[mi][ni], a[mi], b[ni]);
        }
        __syncthreads();
    }
    // Epilogue: + bd, store
    #pragma unroll
    for (int mi = 0; mi < 4; mi++) {
        int r0 = i0 + wr * 64 + mi * 16 + (lane >> 2);
        #pragma unroll
        for (int ni = 0; ni < 4; ni++) {
            int cb = n0 + wc * 32 + ni * 8 + ((lane & 3) << 1);
            if (cb < VOCAB) {     // VOCAB even, cb even -> covers cb+1 too
                float b0v = bd[cb], b1v = bd[cb + 1];
                out[(size_t)r0 * VOCAB + cb]           = acc[mi][ni][0] + b0v;
                out[(size_t)r0 * VOCAB + cb + 1]       = acc[mi][ni][1] + b1v;
                out[(size_t)(r0 + 8) * VOCAB + cb]     = acc[mi][ni][2] + b0v;
                out[(size_t)(r0 + 8) * VOCAB + cb + 1] = acc[mi][ni][3] + b1v;
            }
        }
    }
}

// ---------------------------------------------------------------------------
// kernel_launch: mx gather -> register-resident clustered scan -> tf32 proj
// Inputs (metadata order): tokens, h0, kernel, rkernel, bias, Wd, bd
// ---------------------------------------------------------------------------
extern "C" void kernel_launch(void* const* d_in, const int* in_sizes, int n_in,
                              void* d_out, int out_size) {
    const int*   tokens = (const int*)  d_in[0];
    const float* h0     = (const float*)d_in[1];
    const float* Wk     = (const float*)d_in[2];
    const float* rker   = (const float*)d_in[3];
    const float* bias   = (const float*)d_in[4];
    const float* Wd     = (const float*)d_in[5];
    const float* bd     = (const float*)d_in[6];
    float* out = (float*)d_out;

    const long hl_need = (long)VOCAB * T_STEPS * BATCH + (long)BATCH * HID;
    int write_hl = ((long)out_size >= hl_need) ? 1 : 0;

    // 1) embed gather: T*B*G3 / 256 = 49152 blocks
    mx_kernel<<<(T_STEPS * BATCH * G3) / 256, 256>>>(tokens, Wk, bias);
    // 2) scan: 16 clusters x 8 CTAs x 256 threads
    scan_kernel<<<128, 256>>>(h0, rker, bias, out, write_hl);
    // 3) projection: 40 x 128 tiles of 128x128
    proj_kernel<<<dim3((VOCAB + 127) / 128, (T_STEPS * BATCH) / 128), 256>>>(Wd, bd, out);
}

// round 10
// speedup vs baseline: 1.0957x; 1.0957x over previous
#include <cuda_runtime.h>
#include <cstdint>
#include <math.h>

#define T_STEPS 256
#define BATCH   64
#define HID     256
#define G3      768           // 3*HID
#define VOCAB   5000

typedef unsigned long long u64;

// Scratch (static __device__ arrays: allowed; no runtime allocation)
__device__ __align__(16) float g_MX[(size_t)T_STEPS * BATCH * G3];   // [t][b][3H]
__device__ __align__(16) float g_Y [(size_t)T_STEPS * BATCH * HID];  // [t][b][H]

// ---------------------------------------------------------------------------
// Kernel 1: MX[t][b][n] = kernel[tokens[b][t]][n] + b_in[n]   (gather)
// ---------------------------------------------------------------------------
__global__ void mx_kernel(const int* __restrict__ tokens,
                          const float* __restrict__ Wk,
                          const float* __restrict__ bias) {
    int idx = blockIdx.x * 256 + threadIdx.x;       // exactly T*B*G3 threads
    int n  = idx % G3;
    int tb = idx / G3;
    int b  = tb % BATCH;
    int t  = tb / BATCH;
    int tok = tokens[b * T_STEPS + t];
    g_MX[idx] = Wk[(size_t)tok * G3 + n] + bias[n];
}

// ---------------------------------------------------------------------------
// Common helpers
// ---------------------------------------------------------------------------
__device__ __forceinline__ uint32_t smem_u32(const void* p) {
    uint32_t a;
    asm("{ .reg .u64 t; cvta.to.shared.u64 t, %1; cvt.u32.u64 %0, t; }"
        : "=r"(a) : "l"(p));
    return a;
}
__device__ __forceinline__ void st_cluster_f32(uint32_t laddr, int rank, float v) {
    uint32_t ra;
    asm volatile("mapa.shared::cluster.u32 %0, %1, %2;" : "=r"(ra) : "r"(laddr), "r"(rank));
    asm volatile("st.shared::cluster.f32 [%0], %1;" :: "r"(ra), "f"(v) : "memory");
}
__device__ __forceinline__ u64 fma2(u64 a, u64 b, u64 c) {
    u64 d;
    asm("fma.rn.f32x2 %0, %1, %2, %3;" : "=l"(d) : "l"(a), "l"(b), "l"(c));
    return d;
}
__device__ __forceinline__ u64 packf2(float lo, float hi) {
    return (u64)__float_as_uint(lo) | ((u64)__float_as_uint(hi) << 32);
}
__device__ __forceinline__ float sumf2(u64 p) {
    return __uint_as_float((unsigned)p) + __uint_as_float((unsigned)(p >> 32));
}
__device__ __forceinline__ float sigmoidf_(float x) { return 1.0f / (1.0f + __expf(-x)); }
__device__ __forceinline__ uint32_t f2tf(float f) {
    uint32_t u;
    asm("cvt.rna.tf32.f32 %0, %1;" : "=r"(u) : "f"(f));
    return u;
}

// ---------------------------------------------------------------------------
// Kernel 2: GRU scan (UNCHANGED from passing R8)
// ---------------------------------------------------------------------------
#define HPAD 288

__global__ void __cluster_dims__(8, 1, 1) __launch_bounds__(256, 1) scan_kernel(
    const float* __restrict__ h0,
    const float* __restrict__ rkernel,
    const float* __restrict__ bias,
    float* __restrict__ out, int write_hlast)
{
    __shared__ float hb[2][4][HPAD];     // [parity][seq][padded col]
    const int tid = threadIdx.x;         // = jj*8 + o
    const int jj = tid >> 3;
    const int o  = tid & 7;
    uint32_t crank;
    asm("mov.u32 %0, %%cluster_ctarank;" : "=r"(crank));
    const int cid  = blockIdx.x >> 3;
    const int seq0 = cid * 4;
    const int c    = (int)crank * 32 + jj;
    const int kbase = o * 32;

    u64 w2[3][16];
    #pragma unroll
    for (int g = 0; g < 3; ++g)
        #pragma unroll
        for (int ii = 0; ii < 16; ++ii) {
            float a = rkernel[(size_t)(kbase + 2 * ii)     * G3 + g * HID + c];
            float b = rkernel[(size_t)(kbase + 2 * ii + 1) * G3 + g * HID + c];
            w2[g][ii] = packf2(a, b);
        }
    const float brz = bias[G3 + c];
    const float brr = bias[G3 + HID + c];
    const float brh = bias[G3 + 2 * HID + c];

    for (int e = tid; e < 4 * HID; e += 256) {
        int s = e >> 8, k = e & 255;
        hb[0][s][k + ((k >> 5) << 2)] = h0[(size_t)(seq0 + s) * HID + k];
    }
    const uint32_t hb_base = smem_u32(&hb[0][0][0]);
    const int padc = (int)crank * 36 + jj;
    __syncthreads();
    asm volatile("barrier.cluster.arrive.aligned;" ::: "memory");
    asm volatile("barrier.cluster.wait.aligned;"   ::: "memory");

    for (int t = 0; t < T_STEPS; ++t) {
        const int cur = t & 1, nxt = cur ^ 1;
        const float* mxp = g_MX + ((size_t)t * BATCH + seq0) * G3 + c;
        float mxz[4], mxr[4], mxh[4];
        #pragma unroll
        for (int s = 0; s < 4; ++s) {
            mxz[s] = mxp[(size_t)s * G3];
            mxr[s] = mxp[(size_t)s * G3 + HID];
            mxh[s] = mxp[(size_t)s * G3 + 2 * HID];
        }
        u64 acc[3][4];
        #pragma unroll
        for (int g = 0; g < 3; ++g)
            #pragma unroll
            for (int s = 0; s < 4; ++s) acc[g][s] = 0ull;
        #pragma unroll
        for (int s = 0; s < 4; ++s) {
            const float* hrow = &hb[cur][s][o * 36];
            #pragma unroll
            for (int q = 0; q < 8; ++q) {
                ulonglong2 hp = *reinterpret_cast<const ulonglong2*>(hrow + q * 4);
                #pragma unroll
                for (int g = 0; g < 3; ++g) {
                    acc[g][s] = fma2(w2[g][2 * q],     hp.x, acc[g][s]);
                    acc[g][s] = fma2(w2[g][2 * q + 1], hp.y, acc[g][s]);
                }
            }
        }
        float red[12];
        #pragma unroll
        for (int g = 0; g < 3; ++g)
            #pragma unroll
            for (int s = 0; s < 4; ++s) red[g * 4 + s] = sumf2(acc[g][s]);
        #pragma unroll
        for (int m = 1; m <= 4; m <<= 1)
            #pragma unroll
            for (int v = 0; v < 12; ++v)
                red[v] += __shfl_xor_sync(0xFFFFFFFFu, red[v], m);

        float hn[4];
        #pragma unroll
        for (int s = 0; s < 4; ++s) {
            float az = red[s], ar = red[4 + s], ah = red[8 + s];
            float z = sigmoidf_(mxz[s] + az + brz);
            float r = sigmoidf_(mxr[s] + ar + brr);
            float cand = tanhf(mxh[s] + r * (ah + brh));
            float hp0 = hb[cur][s][padc];
            hn[s] = z * hp0 + (1.0f - z) * cand;
        }
        #pragma unroll
        for (int s = 0; s < 4; ++s) {
            uint32_t la = hb_base + (uint32_t)(((nxt * 4 + s) * HPAD + padc) * 4);
            st_cluster_f32(la, o, hn[s]);
        }
        asm volatile("barrier.cluster.arrive.aligned;" ::: "memory");
        if (o == 0) {
            #pragma unroll
            for (int s = 0; s < 4; ++s)
                g_Y[((size_t)t * BATCH + seq0 + s) * HID + c] = hn[s];
            if (write_hlast && t == T_STEPS - 1) {
                size_t hl = (size_t)VOCAB * (T_STEPS * BATCH);
                #pragma unroll
                for (int s = 0; s < 4; ++s)
                    out[hl + (size_t)(seq0 + s) * HID + c] = hn[s];
            }
        }
        asm volatile("barrier.cluster.wait.aligned;" ::: "memory");
    }
}

// ---------------------------------------------------------------------------
// Kernel 3: out = Y[16384,256] @ Wd[256,5000] + bd, tf32 mma.sync (m16n8k8).
// FRAGMENT-ORDER smem layout: each thread's operands are contiguous ->
// mainloop = conflict-free LDS.128 (A) / LDS.64 (B) instead of conflicted
// scalar LDS.  128x128 tiles, BK=32, 8 warps (2x4), warp tile 64x32.
//
// A frag storage: idx = (((wr*4+mi)*4 + kkidx)*32 + lane)*4 + regpos
//   lane = (row&7)*4 + (k&3); regpos = ((row>>3)&1) + 2*((k>>2)&1)
// B frag storage: idx = ((((wc*4+ni)*4 + kkidx)*32 + lane)*2 + regpos
//   lane = (n&7)*4 + (k&3); regpos = (k>>2)&1
// ---------------------------------------------------------------------------
__device__ __forceinline__ void mma_tf32(float d[4], const uint32_t a[4], const uint32_t b[2]) {
    asm volatile(
        "mma.sync.aligned.m16n8k8.row.col.f32.tf32.tf32.f32 "
        "{%0,%1,%2,%3}, {%4,%5,%6,%7}, {%8,%9}, {%0,%1,%2,%3};\n"
        : "+f"(d[0]), "+f"(d[1]), "+f"(d[2]), "+f"(d[3])
        : "r"(a[0]), "r"(a[1]), "r"(a[2]), "r"(a[3]), "r"(b[0]), "r"(b[1]));
}

__global__ void __launch_bounds__(256) proj_kernel(
    const float* __restrict__ Wd, const float* __restrict__ bd,
    float* __restrict__ out)
{
    __shared__ __align__(16) uint32_t As[4096];   // A fragments, 16KB
    __shared__ __align__(16) uint32_t Bs[4096];   // B fragments, 16KB
    const int tid  = threadIdx.x;
    const int lane = tid & 31, wid = tid >> 5;
    const int wr = wid >> 2, wc = wid & 3;        // warp grid 2x4
    const int n0 = blockIdx.x * 128;
    const int i0 = blockIdx.y * 128;

    float acc[4][4][4];
    #pragma unroll
    for (int mi = 0; mi < 4; mi++)
        #pragma unroll
        for (int ni = 0; ni < 4; ni++)
            #pragma unroll
            for (int q = 0; q < 4; q++) acc[mi][ni][q] = 0.0f;

    for (int k0 = 0; k0 < HID; k0 += 32) {
        // ---- A fill: Y[i0+row][k0+k4..k4+3] -> fragment scatter ----
        #pragma unroll
        for (int it = 0; it < 4; ++it) {
            int g   = tid + it * 256;             // 0..1023
            int row = g >> 3;
            int k4  = (g & 7) << 2;
            float4 v = *reinterpret_cast<const float4*>(
                &g_Y[(size_t)(i0 + row) * HID + k0 + k4]);
            int awr = row >> 6, ami = (row >> 4) & 3, ar8 = (row >> 3) & 1;
            int alr = row & 7;
            int kkidx = k4 >> 3;
            int khalf = (k4 >> 2) & 1;
            int base = (((awr * 4 + ami) * 4 + kkidx) * 32) * 4 + (alr * 4) * 4
                       + (ar8 + 2 * khalf);
            As[base]      = f2tf(v.x);            // lane+0, stride 4 words
            As[base + 4]  = f2tf(v.y);
            As[base + 8]  = f2tf(v.z);
            As[base + 12] = f2tf(v.w);
        }
        // ---- B fill: Wd[k0+k4+e][n0+n] -> fragment scatter (zero pad) ----
        #pragma unroll
        for (int it = 0; it < 4; ++it) {
            int g  = tid + it * 256;              // 0..1023
            int n  = g & 127;
            int k4 = (g >> 7) << 2;               // 0..28
            int col = n0 + n;
            float f0 = 0.f, f1 = 0.f, f2v = 0.f, f3 = 0.f;
            if (col < VOCAB) {
                f0  = Wd[(size_t)(k0 + k4)     * VOCAB + col];
                f1  = Wd[(size_t)(k0 + k4 + 1) * VOCAB + col];
                f2v = Wd[(size_t)(k0 + k4 + 2) * VOCAB + col];
                f3  = Wd[(size_t)(k0 + k4 + 3) * VOCAB + col];
            }
            int bwc = n >> 5, bni = (n >> 3) & 3, bl = n & 7;
            int kkidx = k4 >> 3;
            int regpos = (k4 >> 2) & 1;
            int base = ((((bwc * 4 + bni) * 4 + kkidx) * 32) + bl * 4) * 2 + regpos;
            Bs[base]     = f2tf(f0);              // lane+0, stride 2 words
            Bs[base + 2] = f2tf(f1);
            Bs[base + 4] = f2tf(f2v);
            Bs[base + 6] = f2tf(f3);
        }
        __syncthreads();

        // ---- mainloop: conflict-free vector LDS + HMMA ----
        #pragma unroll
        for (int kkidx = 0; kkidx < 4; ++kkidx) {
            uint32_t a[4][4], b[4][2];
            #pragma unroll
            for (int mi = 0; mi < 4; mi++) {
                uint4 av = *reinterpret_cast<const uint4*>(
                    &As[(((wr * 4 + mi) * 4 + kkidx) * 32 + lane) * 4]);
                a[mi][0] = av.x; a[mi][1] = av.y; a[mi][2] = av.z; a[mi][3] = av.w;
            }
            #pragma unroll
            for (int ni = 0; ni < 4; ni++) {
                uint2 bv = *reinterpret_cast<const uint2*>(
                    &Bs[(((wc * 4 + ni) * 4 + kkidx) * 32 + lane) * 2]);
                b[ni][0] = bv.x; b[ni][1] = bv.y;
            }
            #pragma unroll
            for (int mi = 0; mi < 4; mi++)
                #pragma unroll
                for (int ni = 0; ni < 4; ni++)
                    mma_tf32(acc[mi][ni], a[mi], b[ni]);
        }
        __syncthreads();
    }

    // ---- Epilogue: + bd, direct STG (32B-aligned sectors) ----
    #pragma unroll
    for (int mi = 0; mi < 4; mi++) {
        int r0 = i0 + wr * 64 + mi * 16 + (lane >> 2);
        #pragma unroll
        for (int ni = 0; ni < 4; ni++) {
            int cb = n0 + wc * 32 + ni * 8 + ((lane & 3) << 1);
            if (cb < VOCAB) {     // VOCAB even, cb even -> covers cb+1 too
                float b0v = bd[cb], b1v = bd[cb + 1];
                out[(size_t)r0 * VOCAB + cb]           = acc[mi][ni][0] + b0v;
                out[(size_t)r0 * VOCAB + cb + 1]       = acc[mi][ni][1] + b1v;
                out[(size_t)(r0 + 8) * VOCAB + cb]     = acc[mi][ni][2] + b0v;
                out[(size_t)(r0 + 8) * VOCAB + cb + 1] = acc[mi][ni][3] + b1v;
            }
        }
    }
}

// ---------------------------------------------------------------------------
// kernel_launch: mx gather -> clustered scan -> fragment-layout tf32 proj
// Inputs (metadata order): tokens, h0, kernel, rkernel, bias, Wd, bd
// ---------------------------------------------------------------------------
extern "C" void kernel_launch(void* const* d_in, const int* in_sizes, int n_in,
                              void* d_out, int out_size) {
    const int*   tokens = (const int*)  d_in[0];
    const float* h0     = (const float*)d_in[1];
    const float* Wk     = (const float*)d_in[2];
    const float* rker   = (const float*)d_in[3];
    const float* bias   = (const float*)d_in[4];
    const float* Wd     = (const float*)d_in[5];
    const float* bd     = (const float*)d_in[6];
    float* out = (float*)d_out;

    const long hl_need = (long)VOCAB * T_STEPS * BATCH + (long)BATCH * HID;
    int write_hl = ((long)out_size >= hl_need) ? 1 : 0;

    // 1) embed gather
    mx_kernel<<<(T_STEPS * BATCH * G3) / 256, 256>>>(tokens, Wk, bias);
    // 2) scan: 16 clusters x 8 CTAs x 256 threads
    scan_kernel<<<128, 256>>>(h0, rker, bias, out, write_hl);
    // 3) projection: 40 x 128 tiles of 128x128
    proj_kernel<<<dim3((VOCAB + 127) / 128, (T_STEPS * BATCH) / 128), 256>>>(Wd, bd, out);
}

// round 13
// speedup vs baseline: 1.1086x; 1.0117x over previous
#include <cuda_runtime.h>
#include <cstdint>
#include <math.h>

#define T_STEPS 256
#define BATCH   64
#define HID     256
#define G3      768           // 3*HID
#define VOCAB   5000
#define NBLK    40            // ceil(5000/128)

typedef unsigned long long u64;

// Scratch (static __device__ arrays: allowed; no runtime allocation)
__device__ __align__(16) float    g_MX[(size_t)T_STEPS * BATCH * G3];   // [t][b][3H]
__device__ __align__(16) float    g_Y [(size_t)T_STEPS * BATCH * HID];  // [t][b][H]
__device__ __align__(16) uint32_t g_Yt[(size_t)128 * 8 * 4096];         // A frags (tf32)
__device__ __align__(16) uint32_t g_Wt[(size_t)NBLK * 8 * 4096];        // B frags (tf32)

// ---------------------------------------------------------------------------
// Kernel 1: MX[t][b][n] = kernel[tokens[b][t]][n] + b_in[n]   (gather)
// ---------------------------------------------------------------------------
__global__ void mx_kernel(const int* __restrict__ tokens,
                          const float* __restrict__ Wk,
                          const float* __restrict__ bias) {
    int idx = blockIdx.x * 256 + threadIdx.x;
    int n  = idx % G3;
    int tb = idx / G3;
    int b  = tb % BATCH;
    int t  = tb / BATCH;
    int tok = tokens[b * T_STEPS + t];
    g_MX[idx] = Wk[(size_t)tok * G3 + n] + bias[n];
}

// ---------------------------------------------------------------------------
// Common helpers
// ---------------------------------------------------------------------------
__device__ __forceinline__ uint32_t smem_u32(const void* p) {
    uint32_t a;
    asm("{ .reg .u64 t; cvta.to.shared.u64 t, %1; cvt.u32.u64 %0, t; }"
        : "=r"(a) : "l"(p));
    return a;
}
__device__ __forceinline__ void st_cluster_f32(uint32_t laddr, int rank, float v) {
    uint32_t ra;
    asm volatile("mapa.shared::cluster.u32 %0, %1, %2;" : "=r"(ra) : "r"(laddr), "r"(rank));
    asm volatile("st.shared::cluster.f32 [%0], %1;" :: "r"(ra), "f"(v) : "memory");
}
__device__ __forceinline__ u64 fma2(u64 a, u64 b, u64 c) {
    u64 d;
    asm("fma.rn.f32x2 %0, %1, %2, %3;" : "=l"(d) : "l"(a), "l"(b), "l"(c));
    return d;
}
__device__ __forceinline__ u64 packf2(float lo, float hi) {
    return (u64)__float_as_uint(lo) | ((u64)__float_as_uint(hi) << 32);
}
__device__ __forceinline__ float sumf2(u64 p) {
    return __uint_as_float((unsigned)p) + __uint_as_float((unsigned)(p >> 32));
}
__device__ __forceinline__ float sigmoidf_(float x) { return 1.0f / (1.0f + __expf(-x)); }
__device__ __forceinline__ uint32_t f2tf(float f) {
    uint32_t u;
    asm("cvt.rna.tf32.f32 %0, %1;" : "=r"(u) : "f"(f));
    return u;
}

// ---------------------------------------------------------------------------
// Kernel 2: GRU scan (UNCHANGED from passing R8/R10)
// ---------------------------------------------------------------------------
#define HPAD 288

__global__ void __cluster_dims__(8, 1, 1) __launch_bounds__(256, 1) scan_kernel(
    const float* __restrict__ h0,
    const float* __restrict__ rkernel,
    const float* __restrict__ bias,
    float* __restrict__ out, int write_hlast)
{
    __shared__ float hb[2][4][HPAD];
    const int tid = threadIdx.x;
    const int jj = tid >> 3;
    const int o  = tid & 7;
    uint32_t crank;
    asm("mov.u32 %0, %%cluster_ctarank;" : "=r"(crank));
    const int cid  = blockIdx.x >> 3;
    const int seq0 = cid * 4;
    const int c    = (int)crank * 32 + jj;
    const int kbase = o * 32;

    u64 w2[3][16];
    #pragma unroll
    for (int g = 0; g < 3; ++g)
        #pragma unroll
        for (int ii = 0; ii < 16; ++ii) {
            float a = rkernel[(size_t)(kbase + 2 * ii)     * G3 + g * HID + c];
            float b = rkernel[(size_t)(kbase + 2 * ii + 1) * G3 + g * HID + c];
            w2[g][ii] = packf2(a, b);
        }
    const float brz = bias[G3 + c];
    const float brr = bias[G3 + HID + c];
    const float brh = bias[G3 + 2 * HID + c];

    for (int e = tid; e < 4 * HID; e += 256) {
        int s = e >> 8, k = e & 255;
        hb[0][s][k + ((k >> 5) << 2)] = h0[(size_t)(seq0 + s) * HID + k];
    }
    const uint32_t hb_base = smem_u32(&hb[0][0][0]);
    const int padc = (int)crank * 36 + jj;
    __syncthreads();
    asm volatile("barrier.cluster.arrive.aligned;" ::: "memory");
    asm volatile("barrier.cluster.wait.aligned;"   ::: "memory");

    for (int t = 0; t < T_STEPS; ++t) {
        const int cur = t & 1, nxt = cur ^ 1;
        const float* mxp = g_MX + ((size_t)t * BATCH + seq0) * G3 + c;
        float mxz[4], mxr[4], mxh[4];
        #pragma unroll
        for (int s = 0; s < 4; ++s) {
            mxz[s] = mxp[(size_t)s * G3];
            mxr[s] = mxp[(size_t)s * G3 + HID];
            mxh[s] = mxp[(size_t)s * G3 + 2 * HID];
        }
        u64 acc[3][4];
        #pragma unroll
        for (int g = 0; g < 3; ++g)
            #pragma unroll
            for (int s = 0; s < 4; ++s) acc[g][s] = 0ull;
        #pragma unroll
        for (int s = 0; s < 4; ++s) {
            const float* hrow = &hb[cur][s][o * 36];
            #pragma unroll
            for (int q = 0; q < 8; ++q) {
                ulonglong2 hp = *reinterpret_cast<const ulonglong2*>(hrow + q * 4);
                #pragma unroll
                for (int g = 0; g < 3; ++g) {
                    acc[g][s] = fma2(w2[g][2 * q],     hp.x, acc[g][s]);
                    acc[g][s] = fma2(w2[g][2 * q + 1], hp.y, acc[g][s]);
                }
            }
        }
        float red[12];
        #pragma unroll
        for (int g = 0; g < 3; ++g)
            #pragma unroll
            for (int s = 0; s < 4; ++s) red[g * 4 + s] = sumf2(acc[g][s]);
        #pragma unroll
        for (int m = 1; m <= 4; m <<= 1)
            #pragma unroll
            for (int v = 0; v < 12; ++v)
                red[v] += __shfl_xor_sync(0xFFFFFFFFu, red[v], m);

        float hn[4];
        #pragma unroll
        for (int s = 0; s < 4; ++s) {
            float az = red[s], ar = red[4 + s], ah = red[8 + s];
            float z = sigmoidf_(mxz[s] + az + brz);
            float r = sigmoidf_(mxr[s] + ar + brr);
            float cand = tanhf(mxh[s] + r * (ah + brh));
            float hp0 = hb[cur][s][padc];
            hn[s] = z * hp0 + (1.0f - z) * cand;
        }
        #pragma unroll
        for (int s = 0; s < 4; ++s) {
            uint32_t la = hb_base + (uint32_t)(((nxt * 4 + s) * HPAD + padc) * 4);
            st_cluster_f32(la, o, hn[s]);
        }
        asm volatile("barrier.cluster.arrive.aligned;" ::: "memory");
        if (o == 0) {
            #pragma unroll
            for (int s = 0; s < 4; ++s)
                g_Y[((size_t)t * BATCH + seq0 + s) * HID + c] = hn[s];
            if (write_hlast && t == T_STEPS - 1) {
                size_t hl = (size_t)VOCAB * (T_STEPS * BATCH);
                #pragma unroll
                for (int s = 0; s < 4; ++s)
                    out[hl + (size_t)(seq0 + s) * HID + c] = hn[s];
            }
        }
        asm volatile("barrier.cluster.wait.aligned;" ::: "memory");
    }
}

// ---------------------------------------------------------------------------
// Prep A: g_Y -> g_Yt tf32 fragment order.
// uint4 id u: lane=u&31, frag=(u>>5)&31, tile=u>>10 (tile = mblk*8+ch)
//   r = mblk*128 + (frag>>2)*16 + (lane>>2), k = ch*32 + (frag&3)*8 + (lane&3)
//   words = {Y[r][k], Y[r+8][k], Y[r][k+4], Y[r+8][k+4]}
// ---------------------------------------------------------------------------
__global__ void __launch_bounds__(256) prepY_kernel() {
    int u = blockIdx.x * 256 + threadIdx.x;     // 0 .. 128*8*1024-1
    int lane = u & 31;
    int frag = (u >> 5) & 31;
    int tile = u >> 10;
    int ch   = tile & 7;
    int mblk = tile >> 3;
    int r = mblk * 128 + (frag >> 2) * 16 + (lane >> 2);
    int k = ch * 32 + (frag & 3) * 8 + (lane & 3);
    const float* yr0 = &g_Y[(size_t)r * HID + k];
    uint4 w;
    w.x = f2tf(yr0[0]);
    w.y = f2tf(yr0[8 * HID]);
    w.z = f2tf(yr0[4]);
    w.w = f2tf(yr0[8 * HID + 4]);
    reinterpret_cast<uint4*>(g_Yt)[u] = w;
}

// ---------------------------------------------------------------------------
// Prep B: Wd -> g_Wt tf32 fragment order (zero-padded past VOCAB).
// uint2 id v: lane=v&31, frag=(v>>5)&63, tile=v>>11 (tile = nblk*8+ch)
//   col = nblk*128 + (frag>>2)*8 + (lane>>2), k = ch*32 + (frag&3)*8 + (lane&3)
//   words = {Wd[k][col], Wd[k+4][col]}
// ---------------------------------------------------------------------------
__global__ void __launch_bounds__(256) prepW_kernel(const float* __restrict__ Wd) {
    int v = blockIdx.x * 256 + threadIdx.x;     // 0 .. NBLK*8*2048-1
    int lane = v & 31;
    int frag = (v >> 5) & 63;
    int tile = v >> 11;
    int ch   = tile & 7;
    int nblk = tile >> 3;
    int col = nblk * 128 + (frag >> 2) * 8 + (lane >> 2);
    int k   = ch * 32 + (frag & 3) * 8 + (lane & 3);
    uint2 w = make_uint2(0u, 0u);
    if (col < VOCAB) {
        w.x = f2tf(Wd[(size_t)k * VOCAB + col]);
        w.y = f2tf(Wd[(size_t)(k + 4) * VOCAB + col]);
    }
    reinterpret_cast<uint2*>(g_Wt)[v] = w;
}

// ---------------------------------------------------------------------------
// Kernel 3: out = Y @ Wd + bd, tf32 mma.sync, fragments loaded DIRECTLY from
// gmem (fragment-order layout) into registers, double-buffered at k-step
// granularity. No smem, no __syncthreads, no cvt in the mainloop.
// 128x128 tile/CTA, 8 warps (2x4), warp tile 64x32, 32 k-steps of K=8.
// ---------------------------------------------------------------------------
__device__ __forceinline__ void mma_tf32(float d[4], const uint32_t a[4], const uint32_t b[2]) {
    asm volatile(
        "mma.sync.aligned.m16n8k8.row.col.f32.tf32.tf32.f32 "
        "{%0,%1,%2,%3}, {%4,%5,%6,%7}, {%8,%9}, {%0,%1,%2,%3};\n"
        : "+f"(d[0]), "+f"(d[1]), "+f"(d[2]), "+f"(d[3])
        : "r"(a[0]), "r"(a[1]), "r"(a[2]), "r"(a[3]), "r"(b[0]), "r"(b[1]));
}

__global__ void __launch_bounds__(256) proj_kernel(
    const float* __restrict__ bd, float* __restrict__ out)
{
    const int tid  = threadIdx.x;
    const int lane = tid & 31, wid = tid >> 5;
    const int wr = wid >> 2, wc = wid & 3;       // warp grid 2x4
    const int nblk = blockIdx.x;
    const int mblk = blockIdx.y;
    const int n0 = nblk * 128;
    const int i0 = mblk * 128;

    // Per-thread fragment base pointers (uint4 / uint2 units).
    // A elem idx = tileA*1024 + (wr*4+mi)*128 + kk*32 + lane, tileA = mblk*8+ch
    // B elem idx = tileB*2048 + (wc*4+ni)*128 + kk*32 + lane, tileB = nblk*8+ch
    const uint4* baseA = reinterpret_cast<const uint4*>(g_Yt)
                       + (size_t)mblk * 8192 + wr * 512 + lane;
    const uint2* baseB = reinterpret_cast<const uint2*>(g_Wt)
                       + (size_t)nblk * 16384 + wc * 512 + lane;

    float acc[4][4][4];
    #pragma unroll
    for (int mi = 0; mi < 4; mi++)
        #pragma unroll
        for (int ni = 0; ni < 4; ni++)
            #pragma unroll
            for (int q = 0; q < 4; q++) acc[mi][ni][q] = 0.0f;

    uint4 a0[4], a1[4];
    uint2 b0[4], b1[4];

    // load step 0
    {
        const uint4* pa = baseA;               // ch=0, kk=0
        const uint2* pb = baseB;
        #pragma unroll
        for (int mi = 0; mi < 4; mi++) a0[mi] = pa[mi * 128];
        #pragma unroll
        for (int ni = 0; ni < 4; ni++) b0[ni] = pb[ni * 128];
    }

    #pragma unroll
    for (int s = 0; s < 32; s += 2) {
        // prefetch step s+1 into buf1
        {
            int t1 = s + 1;
            int ch = t1 >> 2, kk = t1 & 3;
            const uint4* pa = baseA + ch * 1024 + kk * 32;
            const uint2* pb = baseB + ch * 2048 + kk * 32;
            #pragma unroll
            for (int mi = 0; mi < 4; mi++) a1[mi] = pa[mi * 128];
            #pragma unroll
            for (int ni = 0; ni < 4; ni++) b1[ni] = pb[ni * 128];
        }
        // MMA on buf0 (step s)
        #pragma unroll
        for (int mi = 0; mi < 4; mi++)
            #pragma unroll
            for (int ni = 0; ni < 4; ni++)
                mma_tf32(acc[mi][ni],
                         reinterpret_cast<const uint32_t*>(&a0[mi]),
                         reinterpret_cast<const uint32_t*>(&b0[ni]));
        // prefetch step s+2 into buf0
        if (s + 2 < 32) {
            int t2 = s + 2;
            int ch = t2 >> 2, kk = t2 & 3;
            const uint4* pa = baseA + ch * 1024 + kk * 32;
            const uint2* pb = baseB + ch * 2048 + kk * 32;
            #pragma unroll
            for (int mi = 0; mi < 4; mi++) a0[mi] = pa[mi * 128];
            #pragma unroll
            for (int ni = 0; ni < 4; ni++) b0[ni] = pb[ni * 128];
        }
        // MMA on buf1 (step s+1)
        #pragma unroll
        for (int mi = 0; mi < 4; mi++)
            #pragma unroll
            for (int ni = 0; ni < 4; ni++)
                mma_tf32(acc[mi][ni],
                         reinterpret_cast<const uint32_t*>(&a1[mi]),
                         reinterpret_cast<const uint32_t*>(&b1[ni]));
    }

    // ---- Epilogue: + bd, direct STG ----
    #pragma unroll
    for (int mi = 0; mi < 4; mi++) {
        int r0 = i0 + wr * 64 + mi * 16 + (lane >> 2);
        #pragma unroll
        for (int ni = 0; ni < 4; ni++) {
            int cbn = n0 + wc * 32 + ni * 8 + ((lane & 3) << 1);
            if (cbn < VOCAB) {                 // VOCAB even -> covers cbn+1
                float b0v = bd[cbn], b1v = bd[cbn + 1];
                out[(size_t)r0 * VOCAB + cbn]           = acc[mi][ni][0] + b0v;
                out[(size_t)r0 * VOCAB + cbn + 1]       = acc[mi][ni][1] + b1v;
                out[(size_t)(r0 + 8) * VOCAB + cbn]     = acc[mi][ni][2] + b0v;
                out[(size_t)(r0 + 8) * VOCAB + cbn + 1] = acc[mi][ni][3] + b1v;
            }
        }
    }
}

// ---------------------------------------------------------------------------
// kernel_launch: mx -> prepW -> scan -> prepY -> proj (register-direct)
// Inputs (metadata order): tokens, h0, kernel, rkernel, bias, Wd, bd
// ---------------------------------------------------------------------------
extern "C" void kernel_launch(void* const* d_in, const int* in_sizes, int n_in,
                              void* d_out, int out_size) {
    const int*   tokens = (const int*)  d_in[0];
    const float* h0     = (const float*)d_in[1];
    const float* Wk     = (const float*)d_in[2];
    const float* rker   = (const float*)d_in[3];
    const float* bias   = (const float*)d_in[4];
    const float* Wd     = (const float*)d_in[5];
    const float* bd     = (const float*)d_in[6];
    float* out = (float*)d_out;

    const long hl_need = (long)VOCAB * T_STEPS * BATCH + (long)BATCH * HID;
    int write_hl = ((long)out_size >= hl_need) ? 1 : 0;

    // 1) embed gather
    mx_kernel<<<(T_STEPS * BATCH * G3) / 256, 256>>>(tokens, Wk, bias);
    // 2) Wd -> tf32 fragments (independent of scan)
    prepW_kernel<<<(NBLK * 8 * 2048) / 256, 256>>>(Wd);
    // 3) scan
    scan_kernel<<<128, 256>>>(h0, rker, bias, out, write_hl);
    // 4) Y -> tf32 fragments
    prepY_kernel<<<(128 * 8 * 1024) / 256, 256>>>();
    // 5) projection: register-direct fragments, no smem
    proj_kernel<<<dim3(NBLK, 128), 256>>>(bd, out);
}